// round 9
// baseline (speedup 1.0000x reference)
#include <cuda_runtime.h>
#include <cuda_bf16.h>
#include <math.h>
#include <cstdint>

#define TT  30
#define BBN 2048
#define DD  256
#define DHH 128

typedef unsigned long long u64;
typedef unsigned int       u32;
typedef unsigned short     u16;

#if defined(__CUDA_ARCH_FEAT_SM103_ALL) || defined(__CUDA_ARCH_FEAT_SM100_ALL) || defined(__CUDA_ARCH_FEAT_SM101_ALL)
#define USE_TCGEN05 1
#else
#define USE_TCGEN05 0
#endif

// Fixed softmax shift 64 (proven R7): no overflow (needs s>152), FTZ-dropped
// terms are >=55 e-folds below any row max, log(0) impossible via clamp.
#define SOFT_SHIFT 64.0f
#define L2E        1.4426950408889634f
#define SHIFT_L2E  (-64.0f * 1.4426950408889634f)

// ---------------------------------------------------------------------------
__device__ float g_lse29[BBN];
__device__ float g_nce[TT * 8];
__device__ u64   g_win[BBN];
__device__ int   g_done = 0;
__device__ u16   g_repB[16 * 32768];       // per 128-col chunk: [hi 16K][lo 16K], swizzled
__device__ u16   g_WB[TT * 2 * 32768];     // per (t,khalf): [hi][lo] W^T tile, swizzled
__device__ u16   g_A29B[16 * 32768];       // per 128-row block: [hi][lo] A29, swizzled

// ---------------------------------------------------------------------------
__device__ __forceinline__ u16 f2bu(float f) {
    __nv_bfloat16 b = __float2bfloat16(f);
    return reinterpret_cast<u16&>(b);
}
__device__ __forceinline__ float b2f(u16 u) {
    __nv_bfloat16 b = reinterpret_cast<__nv_bfloat16&>(u);
    return __bfloat162float(b);
}
__device__ __forceinline__ int swz_idx(int m, int k) {
    int byte = (((m >> 3) + ((k >> 6) << 4)) << 10) + ((m & 7) << 7) + ((k & 63) << 1);
    byte ^= (byte >> 3) & 0x70;
    return byte >> 1;
}
__device__ __forceinline__ float ex2f(float x) {
    float r; asm("ex2.approx.ftz.f32 %0, %1;" : "=f"(r) : "f"(x)); return r;
}

// ---------------------------------------------------------------------------
__global__ void k_pre_rep(const float* __restrict__ rep) {
    int idx = blockIdx.x * blockDim.x + threadIdx.x;   // c*128 + k
    int c = idx >> 7, k = idx & 127;
    float v = rep[idx];
    u16 hi = f2bu(v);
    u16 lo = f2bu(v - b2f(hi));
    int cb = c >> 7, cl = c & 127;
    g_repB[cb * 32768 + swz_idx(cl, k)]         = hi;
    g_repB[cb * 32768 + 16384 + swz_idx(cl, k)] = lo;
    if (idx < BBN) g_win[idx] = 0ULL;
}

__global__ void k_pre_w(const float* __restrict__ W) {
    int idx = blockIdx.x * blockDim.x + threadIdx.x;
    int t = idx / (DD * DHH);
    int r = idx - t * DD * DHH;
    int d = r / DHH, h = r - d * DHH;
    float v = W[idx];
    u16 hi = f2bu(v);
    u16 lo = f2bu(v - b2f(hi));
    int half = d >> 7, kl = d & 127;
    int base = t * 65536 + half * 32768;
    g_WB[base + swz_idx(h, kl)]         = hi;
    g_WB[base + 16384 + swz_idx(h, kl)] = lo;
}

#if USE_TCGEN05
// ===========================================================================
__device__ __forceinline__ u32 elect_one_pred() {
    u32 pred;
    asm volatile("{\n\t.reg .pred p;\n\telect.sync _|p, 0xFFFFFFFF;\n\tselp.b32 %0, 1, 0, p;\n\t}" : "=r"(pred));
    return pred;
}
__device__ __forceinline__ u32 smem_to_u32(const void* p) {
    u32 a;
    asm("{ .reg .u64 t; cvta.to.shared.u64 t, %1; cvt.u32.u64 %0, t; }" : "=r"(a) : "l"(p));
    return a;
}
#define TCGEN05_ALLOC(sa, n) \
    asm volatile("tcgen05.alloc.cta_group::1.sync.aligned.shared::cta.b32 [%0], %1;" :: "r"((u32)(sa)), "r"((u32)(n)) : "memory")
#define TCGEN05_DEALLOC(ta, n) \
    asm volatile("tcgen05.dealloc.cta_group::1.sync.aligned.b32 %0, %1;" :: "r"(ta), "r"((u32)(n)))
#define TCGEN05_RELINQ() \
    asm volatile("tcgen05.relinquish_alloc_permit.cta_group::1.sync.aligned;")
#define TCGEN05_COMMIT(mb) \
    asm volatile("tcgen05.commit.cta_group::1.mbarrier::arrive::one.shared::cluster.b64 [%0];" :: "r"((u32)(mb)) : "memory")
#define TCGEN05_FENCE_BEFORE()  asm volatile("tcgen05.fence::before_thread_sync;" ::: "memory")
#define TCGEN05_FENCE_AFTER()   asm volatile("tcgen05.fence::after_thread_sync;" ::: "memory")
#define TCGEN05_WAIT_LD()       asm volatile("tcgen05.wait::ld.sync.aligned;" ::: "memory")
#define FENCE_PROXY()           asm volatile("fence.proxy.async.shared::cta;" ::: "memory")
#define MBARRIER_INIT(mb, cnt) \
    asm volatile("mbarrier.init.shared.b64 [%0], %1;" :: "r"((u32)(mb)), "r"((u32)(cnt)) : "memory")
#define MBARRIER_INVAL(mb) \
    asm volatile("mbarrier.inval.shared.b64 [%0];" :: "r"((u32)(mb)) : "memory")
#define MBARRIER_WAIT_PARITY(mb, ph) do {                                          \
    u32 _m = (u32)(mb); u32 _p = (u32)(ph); u32 _d;                                \
    asm volatile("{\n\t.reg .pred p;\n\t"                                          \
        "mbarrier.try_wait.parity.acquire.cta.shared::cta.b64 p, [%1], %2;\n\t"    \
        "selp.b32 %0, 1, 0, p;\n\t}" : "=r"(_d) : "r"(_m), "r"(_p) : "memory");    \
    if (!_d) {                                                                     \
        asm volatile("{\n\t.reg .pred P1;\n\t"                                     \
        "WL_%=:\n\t"                                                               \
        "mbarrier.try_wait.parity.acquire.cta.shared::cta.b64 P1, [%0], %1, 0x989680;\n\t" \
        "@P1 bra.uni WD_%=;\n\t"                                                   \
        "bra.uni WL_%=;\n\t"                                                       \
        "WD_%=:\n\t}" :: "r"(_m), "r"(_p) : "memory");                             \
    }                                                                              \
} while (0)

#define TCGEN05_LD_32X32B_X32(r, ta) \
    asm volatile( \
        "tcgen05.ld.sync.aligned.32x32b.x32.b32 " \
        "{%0, %1, %2, %3, %4, %5, %6, %7, " \
        " %8, %9, %10, %11, %12, %13, %14, %15, " \
        " %16, %17, %18, %19, %20, %21, %22, %23, " \
        " %24, %25, %26, %27, %28, %29, %30, %31}, [%32];" \
        : "=r"((r)[0]),  "=r"((r)[1]),  "=r"((r)[2]),  "=r"((r)[3]), \
          "=r"((r)[4]),  "=r"((r)[5]),  "=r"((r)[6]),  "=r"((r)[7]), \
          "=r"((r)[8]),  "=r"((r)[9]),  "=r"((r)[10]), "=r"((r)[11]), \
          "=r"((r)[12]), "=r"((r)[13]), "=r"((r)[14]), "=r"((r)[15]), \
          "=r"((r)[16]), "=r"((r)[17]), "=r"((r)[18]), "=r"((r)[19]), \
          "=r"((r)[20]), "=r"((r)[21]), "=r"((r)[22]), "=r"((r)[23]), \
          "=r"((r)[24]), "=r"((r)[25]), "=r"((r)[26]), "=r"((r)[27]), \
          "=r"((r)[28]), "=r"((r)[29]), "=r"((r)[30]), "=r"((r)[31]) \
        : "r"(ta))

__device__ __forceinline__ void mma_f16_ss(u32 d, u64 ad, u64 bd, u32 idesc, u32 en) {
    asm volatile(
        "{\n\t.reg .pred p;\n\tsetp.ne.u32 p, %5, 0;\n\t"
        "tcgen05.mma.cta_group::1.kind::f16 [%0], %1, %2, %3, {%4, %4, %4, %4}, p;\n\t}"
        :: "r"(d), "l"(ad), "l"(bd), "r"(idesc), "r"(0u), "r"(en) : "memory");
}

static constexpr u64 DESC_BASE =
    (u64(2) << 61) | (u64(1) << 46) | (u64(64) << 32) | (u64(1) << 16);
#define MK_DESC(a) (DESC_BASE | ((u64)((a) >> 4) & 0x3FFF))
#define IDESC 0x8200490u     // F32 accum, BF16xBF16, M=128, N=128

__device__ __forceinline__ void mma_pass8(u32 d, u64 ad, u64 bd, u32 en0) {
#pragma unroll
    for (int j = 0; j < 8; ++j) {
        u64 off = (u64)((j >> 2) * 1024 + (j & 3) * 2);
        mma_f16_ss(d, ad + off, bd + off, IDESC, j == 0 ? en0 : 1u);
    }
}

__device__ __forceinline__ void copy32k(char* dst, const void* src, int tid) {
    const float4* s = (const float4*)src;
    float4* d = (float4*)dst;
#pragma unroll
    for (int i = 0; i < 8; ++i) d[tid + i * 256] = s[tid + i * 256];
}
#endif  // USE_TCGEN05

// ---------------------------------------------------------------------------
// SMEM maps
// ---------------------------------------------------------------------------
#define SM_TMEMPTR 0
#define SM_MG      8
#define SM_FS0     16
#define SM_DIAG    64        // 256 f32 (1024B)
#define SM_MS      1152      // 512 f32 (2048B)
#define SM_RED     3264      // 8 f32
#define SM_A0      4096      // 32KB: E tile0 / A-hi tile0
#define SM_A1      36864     // 32KB: E tile1 / A-hi tile1
#define SM_B0      69632     // 32KB: W-hi / B ping
#define SM_B1      102400    // 32KB: W-lo / B pong
#define SMEM_MAIN  135168

#define SA_TMEMPTR 0
#define SA_MB      8
#define SA_LAST    16
#define SA_LSE     64
#define SA_RH      1024
#define SA_RL      33792
#define SA_AH      66560
#define SA_AL      99328
#define SMEM_ACC2  132096

#if USE_TCGEN05
// Stage E hi-only, swizzled: 128 rows x 128 k from Et[row_base..][dk..]
__device__ __forceinline__ void stage_E(const float* __restrict__ Et, int row_base, int dk,
                                        u16* __restrict__ hb, int tid) {
    int row = tid >> 1;
    int cs  = (tid & 1) * 64;
    const float4* src = (const float4*)(Et + (size_t)(row_base + row) * DD + dk + cs);
#pragma unroll
    for (int q = 0; q < 16; ++q) {
        float4 v = src[q];
        int k = cs + q * 4;
        uint2 hw = make_uint2((u32)f2bu(v.x) | ((u32)f2bu(v.y) << 16),
                              (u32)f2bu(v.z) | ((u32)f2bu(v.w) << 16));
        *(uint2*)(hb + swz_idx(row, k)) = hw;
    }
}
#endif

// ---------------------------------------------------------------------------
// Main fused kernel: one CTA per (t, 256-row block). grid = (8, 30).
// TMEM: GEMM1 A at cols 0..255; GEMM2 S ping-pong at 0..255 / 256..511.
// ---------------------------------------------------------------------------
__global__ void __launch_bounds__(256, 1)
k_main2(const float* __restrict__ E) {
    extern __shared__ char smc[];
#if USE_TCGEN05
    const u32 sb = smem_to_u32(smc);
    float* sDiag = (float*)(smc + SM_DIAG);   // 256
    float* sMS   = (float*)(smc + SM_MS);     // 512
    float* sRed  = (float*)(smc + SM_RED);    // 8

    const int t      = blockIdx.y;
    const int rbb    = blockIdx.x;            // 256-row block
    const int base_b = rbb * 256;
    const int tid    = threadIdx.x;
    const int wid    = tid >> 5;
    const int lane   = tid & 31;
    const int sub    = wid & 3;
    const int chalf  = wid >> 2;
    const int r_loc  = sub * 32 + lane;       // row within a 128-row tile

    const float* Et = E + (size_t)t * BBN * DD;

    if (wid == 0) TCGEN05_ALLOC(sb + SM_TMEMPTR, 512);
    if (tid == 0) {
        MBARRIER_INIT(sb + SM_MG,  1);
        MBARRIER_INIT(sb + SM_FS0, 1);
    }
    __syncthreads();
    u32 tb;
    asm volatile("ld.shared.b32 %0, [%1];" : "=r"(tb) : "r"(sb + SM_TMEMPTR));

    const u64 dA0 = MK_DESC(sb + SM_A0);
    const u64 dA1 = MK_DESC(sb + SM_A1);
    const u64 dB0 = MK_DESC(sb + SM_B0);
    const u64 dB1 = MK_DESC(sb + SM_B1);

    // ------------- GEMM1 (2-pass): A[256x128] = Eh·(Wh+Wl), two K-halves --
#pragma unroll
    for (int kh = 0; kh < 2; ++kh) {
        if (kh == 1) MBARRIER_WAIT_PARITY(sb + SM_MG, 0);
        copy32k(smc + SM_B0, g_WB + t * 65536 + kh * 32768, tid);          // W hi
        copy32k(smc + SM_B1, g_WB + t * 65536 + kh * 32768 + 16384, tid);  // W lo
        stage_E(Et, base_b,       kh * 128, (u16*)(smc + SM_A0), tid);
        stage_E(Et, base_b + 128, kh * 128, (u16*)(smc + SM_A1), tid);
        FENCE_PROXY();
        __syncthreads();
        if (wid == 0 && elect_one_pred()) {
            u32 en = (kh == 0) ? 0u : 1u;
            mma_pass8(tb,       dA0, dB0, en);
            mma_pass8(tb,       dA0, dB1, 1u);
            mma_pass8(tb + 128, dA1, dB0, en);
            mma_pass8(tb + 128, dA1, dB1, 1u);
            TCGEN05_COMMIT(sb + SM_MG);
        }
    }
    MBARRIER_WAIT_PARITY(sb + SM_MG, 1);
    TCGEN05_FENCE_AFTER();
    __syncthreads();

    // ------------- A epilogue: TMEM -> A-hi swizzled into A0/A1 -----------
#pragma unroll
    for (int tt = 0; tt < 2; ++tt) {
        u32 a0[32], a1[32];
        TCGEN05_LD_32X32B_X32(a0, tb + tt * 128 + chalf * 64);
        TCGEN05_LD_32X32B_X32(a1, tb + tt * 128 + chalf * 64 + 32);
        TCGEN05_WAIT_LD();
        u16* hb = (u16*)(smc + (tt ? SM_A1 : SM_A0));
#pragma unroll
        for (int q = 0; q < 8; ++q) {
            int k0 = chalf * 64 + q * 4;
            float v0 = __uint_as_float(a0[4 * q]),     v1 = __uint_as_float(a0[4 * q + 1]);
            float v2 = __uint_as_float(a0[4 * q + 2]), v3 = __uint_as_float(a0[4 * q + 3]);
            *(uint2*)(hb + swz_idx(r_loc, k0)) =
                make_uint2((u32)f2bu(v0) | ((u32)f2bu(v1) << 16),
                           (u32)f2bu(v2) | ((u32)f2bu(v3) << 16));
            int k1 = k0 + 32;
            float w0 = __uint_as_float(a1[4 * q]),     w1 = __uint_as_float(a1[4 * q + 1]);
            float w2 = __uint_as_float(a1[4 * q + 2]), w3 = __uint_as_float(a1[4 * q + 3]);
            *(uint2*)(hb + swz_idx(r_loc, k1)) =
                make_uint2((u32)f2bu(w0) | ((u32)f2bu(w1) << 16),
                           (u32)f2bu(w2) | ((u32)f2bu(w3) << 16));
        }
        if (t == TT - 1) {   // hi/lo split for the accuracy pass
            u16* gh = g_A29B + (rbb * 2 + tt) * 32768;
            u16* gl = gh + 16384;
#pragma unroll
            for (int j = 0; j < 32; ++j) {
                float v = __uint_as_float(a0[j]);
                int k = chalf * 64 + j;
                u16 hi = f2bu(v);
                gh[swz_idx(r_loc, k)] = hi;
                gl[swz_idx(r_loc, k)] = f2bu(v - b2f(hi));
                float w = __uint_as_float(a1[j]);
                int kk = k + 32;
                u16 hi2 = f2bu(w);
                gh[swz_idx(r_loc, kk)] = hi2;
                gl[swz_idx(r_loc, kk)] = f2bu(w - b2f(hi2));
            }
        }
    }
    TCGEN05_FENCE_BEFORE();
    FENCE_PROXY();
    __syncthreads();   // all LDTM of A done before S MMAs overwrite cols 0..255

    // ------------- GEMM2: 16 chunks of 128 cols x 256 rows ---------------
    copy32k(smc + SM_B0, g_repB, tid);       // chunk 0 (hi only)
    FENCE_PROXY();
    __syncthreads();
    if (wid == 0 && elect_one_pred()) {
        mma_pass8(tb,       dA0, dB0, 0u);   // S(0): tile0 cols 0..127
        mma_pass8(tb + 128, dA1, dB0, 0u);   //        tile1 cols 128..255
        TCGEN05_COMMIT(sb + SM_FS0);
    }

    float acc[2][4];
#pragma unroll
    for (int tt = 0; tt < 2; ++tt)
#pragma unroll
        for (int j = 0; j < 4; ++j) acc[tt][j] = 0.0f;

    for (int i = 0; i < 16; ++i) {
        int p = i & 1;
        if (i < 15) {   // stage next chunk's B-hi into the idle buffer
            copy32k(smc + (p ? SM_B0 : SM_B1), g_repB + (i + 1) * 32768, tid);
            FENCE_PROXY();
        }
        MBARRIER_WAIT_PARITY(sb + SM_FS0, p);
        TCGEN05_FENCE_AFTER();
        __syncthreads();
        if (i < 15 && wid == 0 && elect_one_pred()) {
            u64 dB = p ? dB0 : dB1;
            u32 d2 = tb + (p ^ 1) * 256;
            mma_pass8(d2,       dA0, dB, 0u);
            mma_pass8(d2 + 128, dA1, dB, 0u);
            TCGEN05_COMMIT(sb + SM_FS0);
        }

#pragma unroll
        for (int tt = 0; tt < 2; ++tt) {
            u32 v0[32], v1[32];
            TCGEN05_LD_32X32B_X32(v0, tb + p * 256 + tt * 128 + chalf * 64);
            TCGEN05_LD_32X32B_X32(v1, tb + p * 256 + tt * 128 + chalf * 64 + 32);
            TCGEN05_WAIT_LD();

            if (i == rbb * 2 + tt) {   // diagonal: global col == global row
                int jd = r_loc - chalf * 64;
#pragma unroll
                for (int j = 0; j < 32; ++j) {
                    if (j == jd)      sDiag[tt * 128 + r_loc] = __uint_as_float(v0[j]);
                    if (j + 32 == jd) sDiag[tt * 128 + r_loc] = __uint_as_float(v1[j]);
                }
            }

#pragma unroll
            for (int j = 0; j < 32; j += 4) {
                acc[tt][0] += ex2f(fmaf(__uint_as_float(v0[j]),     L2E, SHIFT_L2E));
                acc[tt][1] += ex2f(fmaf(__uint_as_float(v0[j + 1]), L2E, SHIFT_L2E));
                acc[tt][2] += ex2f(fmaf(__uint_as_float(v0[j + 2]), L2E, SHIFT_L2E));
                acc[tt][3] += ex2f(fmaf(__uint_as_float(v0[j + 3]), L2E, SHIFT_L2E));
            }
#pragma unroll
            for (int j = 0; j < 32; j += 4) {
                acc[tt][0] += ex2f(fmaf(__uint_as_float(v1[j]),     L2E, SHIFT_L2E));
                acc[tt][1] += ex2f(fmaf(__uint_as_float(v1[j + 1]), L2E, SHIFT_L2E));
                acc[tt][2] += ex2f(fmaf(__uint_as_float(v1[j + 2]), L2E, SHIFT_L2E));
                acc[tt][3] += ex2f(fmaf(__uint_as_float(v1[j + 3]), L2E, SHIFT_L2E));
            }
        }
        TCGEN05_FENCE_BEFORE();
    }
    __syncthreads();

#pragma unroll
    for (int tt = 0; tt < 2; ++tt)
        sMS[(tt * 128 + r_loc) * 2 + chalf] =
            (acc[tt][0] + acc[tt][1]) + (acc[tt][2] + acc[tt][3]);
    __syncthreads();

    {   // 256 threads -> 256 rows
        float sum = fmaxf(sMS[tid * 2] + sMS[tid * 2 + 1], 1e-35f);
        float lse = SOFT_SHIFT + __logf(sum);
        if (t == TT - 1) g_lse29[base_b + tid] = lse;
        float part = sDiag[tid] - lse;
#pragma unroll
        for (int o = 1; o < 32; o <<= 1)
            part += __shfl_xor_sync(0xffffffffu, part, o);
        if (lane == 0) sRed[wid] = part;
    }
    __syncthreads();
    if (tid == 0) {
        float tot = 0.0f;
#pragma unroll
        for (int r = 0; r < 8; ++r) tot += sRed[r];
        g_nce[t * 8 + rbb] = tot;
    }

    if (tid == 0) {
        MBARRIER_INVAL(sb + SM_MG);
        MBARRIER_INVAL(sb + SM_FS0);
    }
    __syncthreads();
    if (wid == 0) {
        TCGEN05_RELINQ();
        TCGEN05_DEALLOC(tb, 512);
    }
#endif
}

// ---------------------------------------------------------------------------
// Accuracy pass (t=29) on tensor cores + fused finalize (proven)
// ---------------------------------------------------------------------------
__global__ void __launch_bounds__(256, 1)
k_acc2(float* __restrict__ out, int out_size) {
    extern __shared__ char smc[];
#if USE_TCGEN05
    const u32 sb = smem_to_u32(smc);
    float* sLse = (float*)(smc + SA_LSE);
    int*   sLast = (int*)(smc + SA_LAST);

    const int cb  = blockIdx.x;
    const int bb  = blockIdx.y;
    const int tid = threadIdx.x;
    const int wid = tid >> 5;
    const int lane = tid & 31;
    const int sub = wid & 3;
    const int chalf = wid >> 2;
    const int r_loc = sub * 32 + lane;

    if (wid == 0) TCGEN05_ALLOC(sb + SA_TMEMPTR, 128);
    if (tid == 0) MBARRIER_INIT(sb + SA_MB, 1);
    __syncthreads();
    u32 tb;
    asm volatile("ld.shared.b32 %0, [%1];" : "=r"(tb) : "r"(sb + SA_TMEMPTR));

    copy32k(smc + SA_RH, g_repB + cb * 32768, tid);
    copy32k(smc + SA_RL, g_repB + cb * 32768 + 16384, tid);
    copy32k(smc + SA_AH, g_A29B + bb * 32768, tid);
    copy32k(smc + SA_AL, g_A29B + bb * 32768 + 16384, tid);
    if (tid < 128) sLse[tid] = g_lse29[bb * 128 + tid];
    FENCE_PROXY();
    __syncthreads();

    if (wid == 0 && elect_one_pred()) {
        u64 dRH = MK_DESC(sb + SA_RH), dRL = MK_DESC(sb + SA_RL);
        u64 dAH = MK_DESC(sb + SA_AH), dAL = MK_DESC(sb + SA_AL);
        mma_pass8(tb, dRH, dAH, 0u);
        mma_pass8(tb, dRH, dAL, 1u);
        mma_pass8(tb, dRL, dAH, 1u);
        TCGEN05_COMMIT(sb + SA_MB);
    }
    MBARRIER_WAIT_PARITY(sb + SA_MB, 0);
    TCGEN05_FENCE_AFTER();

    u32 v0[32], v1[32];
    TCGEN05_LD_32X32B_X32(v0, tb + chalf * 64);
    TCGEN05_LD_32X32B_X32(v1, tb + chalf * 64 + 32);
    TCGEN05_WAIT_LD();

    int c = cb * 128 + r_loc;
    u64 best = 0ULL;
#pragma unroll
    for (int j = 0; j < 32; ++j) {
        float v = __uint_as_float(v0[j]) - sLse[chalf * 64 + j];
        u32 u = __float_as_uint(v);
        u = (u & 0x80000000u) ? ~u : (u | 0x80000000u);
        u64 key = ((u64)u << 32) | (u32)(bb * 128 + chalf * 64 + j);
        if (key > best) best = key;
    }
#pragma unroll
    for (int j = 0; j < 32; ++j) {
        float v = __uint_as_float(v1[j]) - sLse[chalf * 64 + 32 + j];
        u32 u = __float_as_uint(v);
        u = (u & 0x80000000u) ? ~u : (u | 0x80000000u);
        u64 key = ((u64)u << 32) | (u32)(bb * 128 + chalf * 64 + 32 + j);
        if (key > best) best = key;
    }
    atomicMax(&g_win[c], best);

    TCGEN05_FENCE_BEFORE();
    __syncthreads();
    if (tid == 0) MBARRIER_INVAL(sb + SA_MB);
    __syncthreads();
    if (wid == 0) {
        TCGEN05_RELINQ();
        TCGEN05_DEALLOC(tb, 128);
    }

    __threadfence();
    if (tid == 0) {
        int done = atomicAdd(&g_done, 1);
        *sLast = (done == gridDim.x * gridDim.y - 1);
    }
    __syncthreads();
    if (*sLast) {
        __shared__ double rd[256];
        __shared__ int    ri[256];
        int cnt = 0;
        for (int cc = tid; cc < BBN; cc += 256)
            cnt += ((u32)(g_win[cc] & 0xffffffffULL) == (u32)cc);
        double sum = 0.0;
        for (int i = tid; i < TT * 8; i += 256) sum += (double)g_nce[i];
        rd[tid] = sum; ri[tid] = cnt;
        __syncthreads();
        for (int st = 128; st > 0; st >>= 1) {
            if (tid < st) { rd[tid] += rd[tid + st]; ri[tid] += ri[tid + st]; }
            __syncthreads();
        }
        if (tid == 0) {
            out[0] = (float)ri[0] / (float)BBN;
            out[1] = (float)(rd[0] / (-(double)(BBN * TT)));
            out[2] = (float)BBN;
            out[3] = (float)(BBN * TT);
            for (int i = 4; i < out_size; ++i) out[i] = 0.0f;
            g_done = 0;
        }
    }
#endif
}

// ---------------------------------------------------------------------------
extern "C" void kernel_launch(void* const* d_in, const int* in_sizes, int n_in,
                              void* d_out, int out_size) {
    const float* E   = (const float*)d_in[0];
    const float* rep = (const float*)d_in[1];
    const float* W   = (const float*)d_in[2];
    // d_in[3] = Wk_b: row-constant shift, cancels in both softmaxes
    float* out = (float*)d_out;

    cudaFuncSetAttribute(k_main2, cudaFuncAttributeMaxDynamicSharedMemorySize, SMEM_MAIN);
    cudaFuncSetAttribute(k_acc2,  cudaFuncAttributeMaxDynamicSharedMemorySize, SMEM_ACC2);

    k_pre_rep<<<(BBN * DHH) / 256, 256>>>(rep);
    k_pre_w<<<(TT * DD * DHH) / 256, 256>>>(W);

    dim3 g2(8, TT);
    k_main2<<<g2, 256, SMEM_MAIN>>>(E);

    dim3 g3(16, 16);
    k_acc2<<<g3, 256, SMEM_ACC2>>>(out, out_size);
}

// round 10
// speedup vs baseline: 1.8191x; 1.8191x over previous
#include <cuda_runtime.h>
#include <cuda_bf16.h>
#include <math.h>
#include <cstdint>

#define TT  30
#define BBN 2048
#define DD  256
#define DHH 128

typedef unsigned long long u64;
typedef unsigned int       u32;
typedef unsigned short     u16;

#if defined(__CUDA_ARCH_FEAT_SM103_ALL) || defined(__CUDA_ARCH_FEAT_SM100_ALL) || defined(__CUDA_ARCH_FEAT_SM101_ALL)
#define USE_TCGEN05 1
#else
#define USE_TCGEN05 0
#endif

// Fixed softmax shift 64 (proven R7): no overflow, FTZ-dropped terms >=55
// e-folds below any row max, log(0) impossible via clamp.
#define SOFT_SHIFT 64.0f
#define L2E        1.4426950408889634f
#define SHIFT_L2E  (-64.0f * 1.4426950408889634f)

// ---------------------------------------------------------------------------
__device__ float g_lse29[BBN];
__device__ float g_nce[TT * 16];
__device__ u64   g_win[BBN];
__device__ int   g_done = 0;
__device__ u16   g_repB[16 * 32768];       // per 128-col chunk: [hi 16K][lo 16K], swizzled
__device__ u16   g_WB[TT * 2 * 32768];     // per (t,khalf): [hi][lo] W^T tile, swizzled
__device__ u16   g_A29B[16 * 32768];       // per 128-row block: [hi][lo] A29, swizzled

// ---------------------------------------------------------------------------
__device__ __forceinline__ u16 f2bu(float f) {
    __nv_bfloat16 b = __float2bfloat16(f);
    return reinterpret_cast<u16&>(b);
}
__device__ __forceinline__ float b2f(u16 u) {
    __nv_bfloat16 b = reinterpret_cast<__nv_bfloat16&>(u);
    return __bfloat162float(b);
}
__device__ __forceinline__ int swz_idx(int m, int k) {
    int byte = (((m >> 3) + ((k >> 6) << 4)) << 10) + ((m & 7) << 7) + ((k & 63) << 1);
    byte ^= (byte >> 3) & 0x70;
    return byte >> 1;
}
__device__ __forceinline__ float ex2f(float x) {
    float r; asm("ex2.approx.ftz.f32 %0, %1;" : "=f"(r) : "f"(x)); return r;
}

// ---------------------------------------------------------------------------
// Merged pre-kernel: rep split+swizzle, W split+swizzle, g_win zero.
// ---------------------------------------------------------------------------
__global__ void k_pre(const float* __restrict__ rep, const float* __restrict__ W) {
    int gid = blockIdx.x * blockDim.x + threadIdx.x;
    if (gid < BBN * DHH) {
        int c = gid >> 7, k = gid & 127;
        float v = rep[gid];
        u16 hi = f2bu(v);
        u16 lo = f2bu(v - b2f(hi));
        int cb = c >> 7, cl = c & 127;
        g_repB[cb * 32768 + swz_idx(cl, k)]         = hi;
        g_repB[cb * 32768 + 16384 + swz_idx(cl, k)] = lo;
        if (gid < BBN) g_win[gid] = 0ULL;
    }
    if (gid < TT * DD * DHH) {
        int t = gid / (DD * DHH);
        int r = gid - t * DD * DHH;
        int d = r / DHH, h = r - d * DHH;
        float v = W[gid];
        u16 hi = f2bu(v);
        u16 lo = f2bu(v - b2f(hi));
        int half = d >> 7, kl = d & 127;
        int base = t * 65536 + half * 32768;
        g_WB[base + swz_idx(h, kl)]         = hi;
        g_WB[base + 16384 + swz_idx(h, kl)] = lo;
    }
}

#if USE_TCGEN05
// ===========================================================================
__device__ __forceinline__ u32 elect_one_pred() {
    u32 pred;
    asm volatile("{\n\t.reg .pred p;\n\telect.sync _|p, 0xFFFFFFFF;\n\tselp.b32 %0, 1, 0, p;\n\t}" : "=r"(pred));
    return pred;
}
__device__ __forceinline__ u32 smem_to_u32(const void* p) {
    u32 a;
    asm("{ .reg .u64 t; cvta.to.shared.u64 t, %1; cvt.u32.u64 %0, t; }" : "=r"(a) : "l"(p));
    return a;
}
#define TCGEN05_ALLOC(sa, n) \
    asm volatile("tcgen05.alloc.cta_group::1.sync.aligned.shared::cta.b32 [%0], %1;" :: "r"((u32)(sa)), "r"((u32)(n)) : "memory")
#define TCGEN05_DEALLOC(ta, n) \
    asm volatile("tcgen05.dealloc.cta_group::1.sync.aligned.b32 %0, %1;" :: "r"(ta), "r"((u32)(n)))
#define TCGEN05_RELINQ() \
    asm volatile("tcgen05.relinquish_alloc_permit.cta_group::1.sync.aligned;")
#define TCGEN05_COMMIT(mb) \
    asm volatile("tcgen05.commit.cta_group::1.mbarrier::arrive::one.shared::cluster.b64 [%0];" :: "r"((u32)(mb)) : "memory")
#define TCGEN05_FENCE_BEFORE()  asm volatile("tcgen05.fence::before_thread_sync;" ::: "memory")
#define TCGEN05_FENCE_AFTER()   asm volatile("tcgen05.fence::after_thread_sync;" ::: "memory")
#define TCGEN05_WAIT_LD()       asm volatile("tcgen05.wait::ld.sync.aligned;" ::: "memory")
#define FENCE_PROXY()           asm volatile("fence.proxy.async.shared::cta;" ::: "memory")
#define MBARRIER_INIT(mb, cnt) \
    asm volatile("mbarrier.init.shared.b64 [%0], %1;" :: "r"((u32)(mb)), "r"((u32)(cnt)) : "memory")
#define MBARRIER_INVAL(mb) \
    asm volatile("mbarrier.inval.shared.b64 [%0];" :: "r"((u32)(mb)) : "memory")
#define MBARRIER_EXPECT_TX(mb, bytes) \
    asm volatile("mbarrier.arrive.expect_tx.shared.b64 _, [%0], %1;" :: "r"((u32)(mb)), "r"((u32)(bytes)) : "memory")
#define MBARRIER_WAIT_PARITY(mb, ph) do {                                          \
    u32 _m = (u32)(mb); u32 _p = (u32)(ph); u32 _d;                                \
    asm volatile("{\n\t.reg .pred p;\n\t"                                          \
        "mbarrier.try_wait.parity.acquire.cta.shared::cta.b64 p, [%1], %2;\n\t"    \
        "selp.b32 %0, 1, 0, p;\n\t}" : "=r"(_d) : "r"(_m), "r"(_p) : "memory");    \
    if (!_d) {                                                                     \
        asm volatile("{\n\t.reg .pred P1;\n\t"                                     \
        "WL_%=:\n\t"                                                               \
        "mbarrier.try_wait.parity.acquire.cta.shared::cta.b64 P1, [%0], %1, 0x989680;\n\t" \
        "@P1 bra.uni WD_%=;\n\t"                                                   \
        "bra.uni WL_%=;\n\t"                                                       \
        "WD_%=:\n\t}" :: "r"(_m), "r"(_p) : "memory");                             \
    }                                                                              \
} while (0)

// Plain bulk async copy gmem->smem (pre-swizzled data; no tensor map).
#define BULK_G2S(dst, src, bytes, mb) \
    asm volatile("cp.async.bulk.shared::cta.global.mbarrier::complete_tx::bytes [%0], [%1], %2, [%3];" \
        :: "r"((u32)(dst)), "l"((const void*)(src)), "r"((u32)(bytes)), "r"((u32)(mb)) : "memory")

#define TCGEN05_LD_32X32B_X32(r, ta) \
    asm volatile( \
        "tcgen05.ld.sync.aligned.32x32b.x32.b32 " \
        "{%0, %1, %2, %3, %4, %5, %6, %7, " \
        " %8, %9, %10, %11, %12, %13, %14, %15, " \
        " %16, %17, %18, %19, %20, %21, %22, %23, " \
        " %24, %25, %26, %27, %28, %29, %30, %31}, [%32];" \
        : "=r"((r)[0]),  "=r"((r)[1]),  "=r"((r)[2]),  "=r"((r)[3]), \
          "=r"((r)[4]),  "=r"((r)[5]),  "=r"((r)[6]),  "=r"((r)[7]), \
          "=r"((r)[8]),  "=r"((r)[9]),  "=r"((r)[10]), "=r"((r)[11]), \
          "=r"((r)[12]), "=r"((r)[13]), "=r"((r)[14]), "=r"((r)[15]), \
          "=r"((r)[16]), "=r"((r)[17]), "=r"((r)[18]), "=r"((r)[19]), \
          "=r"((r)[20]), "=r"((r)[21]), "=r"((r)[22]), "=r"((r)[23]), \
          "=r"((r)[24]), "=r"((r)[25]), "=r"((r)[26]), "=r"((r)[27]), \
          "=r"((r)[28]), "=r"((r)[29]), "=r"((r)[30]), "=r"((r)[31]) \
        : "r"(ta))

__device__ __forceinline__ void mma_f16_ss(u32 d, u64 ad, u64 bd, u32 idesc, u32 en) {
    asm volatile(
        "{\n\t.reg .pred p;\n\tsetp.ne.u32 p, %5, 0;\n\t"
        "tcgen05.mma.cta_group::1.kind::f16 [%0], %1, %2, %3, {%4, %4, %4, %4}, p;\n\t}"
        :: "r"(d), "l"(ad), "l"(bd), "r"(idesc), "r"(0u), "r"(en) : "memory");
}

static constexpr u64 DESC_BASE =
    (u64(2) << 61) | (u64(1) << 46) | (u64(64) << 32) | (u64(1) << 16);
#define MK_DESC(a) (DESC_BASE | ((u64)((a) >> 4) & 0x3FFF))
#define IDESC 0x8200490u     // F32 accum, BF16xBF16, M=128, N=128

__device__ __forceinline__ void mma_pass8(u32 d, u64 ad, u64 bd, u32 en0) {
#pragma unroll
    for (int j = 0; j < 8; ++j) {
        u64 off = (u64)((j >> 2) * 1024 + (j & 3) * 2);
        mma_f16_ss(d, ad + off, bd + off, IDESC, j == 0 ? en0 : 1u);
    }
}

__device__ __forceinline__ void copy32k(char* dst, const void* src, int tid) {
    const float4* s = (const float4*)src;
    float4* d = (float4*)dst;
#pragma unroll
    for (int i = 0; i < 8; ++i) d[tid + i * 256] = s[tid + i * 256];
}
#endif  // USE_TCGEN05

// ---------------------------------------------------------------------------
// SMEM map (main kernel)
// ---------------------------------------------------------------------------
#define SM_TMEMPTR 0
#define SM_MG      8         // MMA-done mbar (GEMM1)
#define SM_FS      16        // MMA-done mbar (GEMM2, ping-pong via parity)
#define SM_WF      24        // W bulk-copy full mbar
#define SM_FB(j)   (32 + 8 * (j))   // B chunk full mbars, j=0..3
#define SM_DIAG    64        // 128 f32
#define SM_MS      576       // 256 f32
#define SM_RED     1600      // 4 f32
#define SM_A       4096      // 32KB: E-hi stage / A-hi
#define SM_B(j)    (36864 + 32768 * (j))    // 4 x 32KB B buffers
#define SMEM_MAIN  167936

#define SA_TMEMPTR 0
#define SA_MB      8
#define SA_LAST    16
#define SA_LSE     64
#define SA_RH      1024
#define SA_RL      33792
#define SA_AH      66560
#define SA_AL      99328
#define SMEM_ACC2  132096

#if USE_TCGEN05
__device__ __forceinline__ void stage_E(const float* __restrict__ Et, int base_b, int dk,
                                        char* smc, int tid) {
    int row = tid >> 1;
    int cs  = (tid & 1) * 64;
    const float4* src = (const float4*)(Et + (size_t)(base_b + row) * DD + dk + cs);
    u16* hb = (u16*)(smc + SM_A);
#pragma unroll
    for (int q = 0; q < 16; ++q) {
        float4 v = src[q];
        int k = cs + q * 4;
        uint2 hw = make_uint2((u32)f2bu(v.x) | ((u32)f2bu(v.y) << 16),
                              (u32)f2bu(v.z) | ((u32)f2bu(v.w) << 16));
        *(uint2*)(hb + swz_idx(row, k)) = hw;
    }
}
#endif

// ---------------------------------------------------------------------------
// Main fused kernel: one CTA per (t, 128-row block). R7 skeleton + TMA bulk
// copies (async proxy -> no per-chunk proxy fences) + 4-deep B pipeline.
// ---------------------------------------------------------------------------
__global__ void __launch_bounds__(256, 1)
k_main2(const float* __restrict__ E) {
    extern __shared__ char smc[];
#if USE_TCGEN05
    const u32 sb = smem_to_u32(smc);
    float* sDiag = (float*)(smc + SM_DIAG);
    float* sMS   = (float*)(smc + SM_MS);
    float* sRed  = (float*)(smc + SM_RED);

    const int t      = blockIdx.y;
    const int rb     = blockIdx.x;
    const int base_b = rb * 128;
    const int tid    = threadIdx.x;
    const int wid    = tid >> 5;
    const int lane   = tid & 31;
    const int sub    = wid & 3;
    const int chalf  = wid >> 2;
    const int r_loc  = sub * 32 + lane;

    const float* Et = E + (size_t)t * BBN * DD;

    if (wid == 0) TCGEN05_ALLOC(sb + SM_TMEMPTR, 512);
    if (tid == 0) {
        MBARRIER_INIT(sb + SM_MG, 1);
        MBARRIER_INIT(sb + SM_FS, 1);
        MBARRIER_INIT(sb + SM_WF, 1);
#pragma unroll
        for (int j = 0; j < 4; ++j) MBARRIER_INIT(sb + SM_FB(j), 1);
    }
    __syncthreads();
    u32 tb;
    asm volatile("ld.shared.b32 %0, [%1];" : "=r"(tb) : "r"(sb + SM_TMEMPTR));

    const u64 dA = MK_DESC(sb + SM_A);
    u64 dB[4];
#pragma unroll
    for (int j = 0; j < 4; ++j) dB[j] = MK_DESC(sb + SM_B(j));

    // Kick off W copy (all 4 tiles: hi0,lo0,hi1,lo1 = 128KB) into B0..B3.
    if (wid == 0 && elect_one_pred()) {
        MBARRIER_EXPECT_TX(sb + SM_WF, 131072);
        BULK_G2S(sb + SM_B(0), g_WB + t * 65536, 131072, sb + SM_WF);
    }

    // ------------- GEMM1 (2-pass): A = Eh·(Wh+Wl), two K-halves -----------
    stage_E(Et, base_b, 0, smc, tid);
    FENCE_PROXY();
    __syncthreads();
    if (wid == 0 && elect_one_pred()) {
        MBARRIER_WAIT_PARITY(sb + SM_WF, 0);   // W tiles arrived
        mma_pass8(tb, dA, dB[0], 0u);          // E0 * W0hi
        mma_pass8(tb, dA, dB[1], 1u);          // E0 * W0lo
        TCGEN05_COMMIT(sb + SM_MG);
    }
    MBARRIER_WAIT_PARITY(sb + SM_MG, 0);       // khalf0 MMAs done (A reusable)

    stage_E(Et, base_b, 128, smc, tid);
    FENCE_PROXY();
    __syncthreads();
    if (wid == 0 && elect_one_pred()) {
        mma_pass8(tb, dA, dB[2], 1u);          // E1 * W1hi
        mma_pass8(tb, dA, dB[3], 1u);          // E1 * W1lo
        TCGEN05_COMMIT(sb + SM_MG);
    }
    MBARRIER_WAIT_PARITY(sb + SM_MG, 1);
    TCGEN05_FENCE_AFTER();
    __syncthreads();

    // ------------- A epilogue: TMEM -> A-hi swizzled in SM_A --------------
    {
        u32 a0[32], a1[32];
        TCGEN05_LD_32X32B_X32(a0, tb + chalf * 64);
        TCGEN05_LD_32X32B_X32(a1, tb + chalf * 64 + 32);
        TCGEN05_WAIT_LD();
        u16* hb = (u16*)(smc + SM_A);
#pragma unroll
        for (int q = 0; q < 8; ++q) {
            int k0 = chalf * 64 + q * 4;
            float v0 = __uint_as_float(a0[4 * q]),     v1 = __uint_as_float(a0[4 * q + 1]);
            float v2 = __uint_as_float(a0[4 * q + 2]), v3 = __uint_as_float(a0[4 * q + 3]);
            *(uint2*)(hb + swz_idx(r_loc, k0)) =
                make_uint2((u32)f2bu(v0) | ((u32)f2bu(v1) << 16),
                           (u32)f2bu(v2) | ((u32)f2bu(v3) << 16));
            int k1 = k0 + 32;
            float w0 = __uint_as_float(a1[4 * q]),     w1 = __uint_as_float(a1[4 * q + 1]);
            float w2 = __uint_as_float(a1[4 * q + 2]), w3 = __uint_as_float(a1[4 * q + 3]);
            *(uint2*)(hb + swz_idx(r_loc, k1)) =
                make_uint2((u32)f2bu(w0) | ((u32)f2bu(w1) << 16),
                           (u32)f2bu(w2) | ((u32)f2bu(w3) << 16));
        }
        if (t == TT - 1) {   // hi/lo split for the accuracy pass
            u16* gh = g_A29B + rb * 32768;
            u16* gl = gh + 16384;
#pragma unroll
            for (int j = 0; j < 32; ++j) {
                float v = __uint_as_float(a0[j]);
                int k = chalf * 64 + j;
                u16 hi = f2bu(v);
                gh[swz_idx(r_loc, k)] = hi;
                gl[swz_idx(r_loc, k)] = f2bu(v - b2f(hi));
                float w = __uint_as_float(a1[j]);
                int kk = k + 32;
                u16 hi2 = f2bu(w);
                gh[swz_idx(r_loc, kk)] = hi2;
                gl[swz_idx(r_loc, kk)] = f2bu(w - b2f(hi2));
            }
        }
        TCGEN05_FENCE_BEFORE();
        FENCE_PROXY();       // A-hi generic stores -> visible to async proxy
    }
    __syncthreads();

    // ------------- GEMM2: 16 chunks, 4-deep TMA-fed B pipeline ------------
    if (wid == 0 && elect_one_pred()) {
#pragma unroll
        for (int j = 0; j < 4; ++j) {          // prefetch chunks 0..3
            MBARRIER_EXPECT_TX(sb + SM_FB(j), 32768);
            BULK_G2S(sb + SM_B(j), g_repB + j * 32768, 32768, sb + SM_FB(j));
        }
        MBARRIER_WAIT_PARITY(sb + SM_FB(0), 0);
        mma_pass8(tb + 128, dA, dB[0], 0u);    // S(0) -> T ping
        TCGEN05_COMMIT(sb + SM_FS);
    }

    float acc0 = 0.0f, acc1 = 0.0f, acc2 = 0.0f, acc3 = 0.0f;

    for (int i = 0; i < 16; ++i) {
        int p = i & 1;
        MBARRIER_WAIT_PARITY(sb + SM_FS, p);   // MMA(i) done
        TCGEN05_FENCE_AFTER();
        __syncthreads();                       // T(p^1) fully drained (iter i-1)

        if (wid == 0 && elect_one_pred()) {
            if (i + 4 <= 15) {                 // refill freed buffer i%4
                MBARRIER_EXPECT_TX(sb + SM_FB(i & 3), 32768);
                BULK_G2S(sb + SM_B(i & 3), g_repB + (i + 4) * 32768, 32768,
                         sb + SM_FB(i & 3));
            }
            if (i < 15) {                      // issue MMA(i+1) -> T(p^1)
                int j = (i + 1) & 3;
                MBARRIER_WAIT_PARITY(sb + SM_FB(j), ((i + 1) >> 2) & 1);
                mma_pass8(tb + 128 + 128 * (p ^ 1), dA, dB[j], 0u);
                TCGEN05_COMMIT(sb + SM_FS);
            }
        }

        u32 v0[32], v1[32];
        TCGEN05_LD_32X32B_X32(v0, tb + 128 + 128 * p + chalf * 64);
        TCGEN05_LD_32X32B_X32(v1, tb + 128 + 128 * p + chalf * 64 + 32);
        TCGEN05_WAIT_LD();

        if (i == rb) {   // diagonal capture
            int jd = r_loc - chalf * 64;
#pragma unroll
            for (int j = 0; j < 32; ++j) {
                if (j == jd)      sDiag[r_loc] = __uint_as_float(v0[j]);
                if (j + 32 == jd) sDiag[r_loc] = __uint_as_float(v1[j]);
            }
        }

        // sum += exp(s - 64); 4 independent accumulator chains
#pragma unroll
        for (int j = 0; j < 32; j += 4) {
            acc0 += ex2f(fmaf(__uint_as_float(v0[j]),     L2E, SHIFT_L2E));
            acc1 += ex2f(fmaf(__uint_as_float(v0[j + 1]), L2E, SHIFT_L2E));
            acc2 += ex2f(fmaf(__uint_as_float(v0[j + 2]), L2E, SHIFT_L2E));
            acc3 += ex2f(fmaf(__uint_as_float(v0[j + 3]), L2E, SHIFT_L2E));
        }
#pragma unroll
        for (int j = 0; j < 32; j += 4) {
            acc0 += ex2f(fmaf(__uint_as_float(v1[j]),     L2E, SHIFT_L2E));
            acc1 += ex2f(fmaf(__uint_as_float(v1[j + 1]), L2E, SHIFT_L2E));
            acc2 += ex2f(fmaf(__uint_as_float(v1[j + 2]), L2E, SHIFT_L2E));
            acc3 += ex2f(fmaf(__uint_as_float(v1[j + 3]), L2E, SHIFT_L2E));
        }
        TCGEN05_FENCE_BEFORE();
    }
    __syncthreads();

    sMS[r_loc * 2 + chalf] = (acc0 + acc1) + (acc2 + acc3);
    __syncthreads();

    if (tid < 128) {
        float sum = fmaxf(sMS[tid * 2] + sMS[tid * 2 + 1], 1e-35f);
        float lse = SOFT_SHIFT + __logf(sum);
        if (t == TT - 1) g_lse29[base_b + tid] = lse;
        float part = sDiag[tid] - lse;
#pragma unroll
        for (int o = 1; o < 32; o <<= 1)
            part += __shfl_xor_sync(0xffffffffu, part, o);
        if ((tid & 31) == 0) sRed[tid >> 5] = part;
    }
    __syncthreads();
    if (tid == 0)
        g_nce[t * 16 + rb] = sRed[0] + sRed[1] + sRed[2] + sRed[3];

    if (tid == 0) {
        MBARRIER_INVAL(sb + SM_MG);
        MBARRIER_INVAL(sb + SM_FS);
        MBARRIER_INVAL(sb + SM_WF);
#pragma unroll
        for (int j = 0; j < 4; ++j) MBARRIER_INVAL(sb + SM_FB(j));
    }
    __syncthreads();
    if (wid == 0) {
        TCGEN05_RELINQ();
        TCGEN05_DEALLOC(tb, 512);
    }
#endif
}

// ---------------------------------------------------------------------------
// Accuracy pass (t=29) on tensor cores + fused finalize (proven, unchanged)
// ---------------------------------------------------------------------------
__global__ void __launch_bounds__(256, 1)
k_acc2(float* __restrict__ out, int out_size) {
    extern __shared__ char smc[];
#if USE_TCGEN05
    const u32 sb = smem_to_u32(smc);
    float* sLse = (float*)(smc + SA_LSE);
    int*   sLast = (int*)(smc + SA_LAST);

    const int cb  = blockIdx.x;
    const int bb  = blockIdx.y;
    const int tid = threadIdx.x;
    const int wid = tid >> 5;
    const int lane = tid & 31;
    const int sub = wid & 3;
    const int chalf = wid >> 2;
    const int r_loc = sub * 32 + lane;

    if (wid == 0) TCGEN05_ALLOC(sb + SA_TMEMPTR, 128);
    if (tid == 0) MBARRIER_INIT(sb + SA_MB, 1);
    __syncthreads();
    u32 tb;
    asm volatile("ld.shared.b32 %0, [%1];" : "=r"(tb) : "r"(sb + SA_TMEMPTR));

    copy32k(smc + SA_RH, g_repB + cb * 32768, tid);
    copy32k(smc + SA_RL, g_repB + cb * 32768 + 16384, tid);
    copy32k(smc + SA_AH, g_A29B + bb * 32768, tid);
    copy32k(smc + SA_AL, g_A29B + bb * 32768 + 16384, tid);
    if (tid < 128) sLse[tid] = g_lse29[bb * 128 + tid];
    FENCE_PROXY();
    __syncthreads();

    if (wid == 0 && elect_one_pred()) {
        u64 dRH = MK_DESC(sb + SA_RH), dRL = MK_DESC(sb + SA_RL);
        u64 dAH = MK_DESC(sb + SA_AH), dAL = MK_DESC(sb + SA_AL);
        mma_pass8(tb, dRH, dAH, 0u);
        mma_pass8(tb, dRH, dAL, 1u);
        mma_pass8(tb, dRL, dAH, 1u);
        TCGEN05_COMMIT(sb + SA_MB);
    }
    MBARRIER_WAIT_PARITY(sb + SA_MB, 0);
    TCGEN05_FENCE_AFTER();

    u32 v0[32], v1[32];
    TCGEN05_LD_32X32B_X32(v0, tb + chalf * 64);
    TCGEN05_LD_32X32B_X32(v1, tb + chalf * 64 + 32);
    TCGEN05_WAIT_LD();

    int c = cb * 128 + r_loc;
    u64 best = 0ULL;
#pragma unroll
    for (int j = 0; j < 32; ++j) {
        float v = __uint_as_float(v0[j]) - sLse[chalf * 64 + j];
        u32 u = __float_as_uint(v);
        u = (u & 0x80000000u) ? ~u : (u | 0x80000000u);
        u64 key = ((u64)u << 32) | (u32)(bb * 128 + chalf * 64 + j);
        if (key > best) best = key;
    }
#pragma unroll
    for (int j = 0; j < 32; ++j) {
        float v = __uint_as_float(v1[j]) - sLse[chalf * 64 + 32 + j];
        u32 u = __float_as_uint(v);
        u = (u & 0x80000000u) ? ~u : (u | 0x80000000u);
        u64 key = ((u64)u << 32) | (u32)(bb * 128 + chalf * 64 + 32 + j);
        if (key > best) best = key;
    }
    atomicMax(&g_win[c], best);

    TCGEN05_FENCE_BEFORE();
    __syncthreads();
    if (tid == 0) MBARRIER_INVAL(sb + SA_MB);
    __syncthreads();
    if (wid == 0) {
        TCGEN05_RELINQ();
        TCGEN05_DEALLOC(tb, 128);
    }

    __threadfence();
    if (tid == 0) {
        int done = atomicAdd(&g_done, 1);
        *sLast = (done == gridDim.x * gridDim.y - 1);
    }
    __syncthreads();
    if (*sLast) {
        __shared__ double rd[256];
        __shared__ int    ri[256];
        int cnt = 0;
        for (int cc = tid; cc < BBN; cc += 256)
            cnt += ((u32)(g_win[cc] & 0xffffffffULL) == (u32)cc);
        double sum = 0.0;
        for (int i = tid; i < TT * 16; i += 256) sum += (double)g_nce[i];
        rd[tid] = sum; ri[tid] = cnt;
        __syncthreads();
        for (int st = 128; st > 0; st >>= 1) {
            if (tid < st) { rd[tid] += rd[tid + st]; ri[tid] += ri[tid + st]; }
            __syncthreads();
        }
        if (tid == 0) {
            out[0] = (float)ri[0] / (float)BBN;
            out[1] = (float)(rd[0] / (-(double)(BBN * TT)));
            out[2] = (float)BBN;
            out[3] = (float)(BBN * TT);
            for (int i = 4; i < out_size; ++i) out[i] = 0.0f;
            g_done = 0;
        }
    }
#endif
}

// ---------------------------------------------------------------------------
extern "C" void kernel_launch(void* const* d_in, const int* in_sizes, int n_in,
                              void* d_out, int out_size) {
    const float* E   = (const float*)d_in[0];
    const float* rep = (const float*)d_in[1];
    const float* W   = (const float*)d_in[2];
    // d_in[3] = Wk_b: row-constant shift, cancels in both softmaxes
    float* out = (float*)d_out;

    cudaFuncSetAttribute(k_main2, cudaFuncAttributeMaxDynamicSharedMemorySize, SMEM_MAIN);
    cudaFuncSetAttribute(k_acc2,  cudaFuncAttributeMaxDynamicSharedMemorySize, SMEM_ACC2);

    k_pre<<<(TT * DD * DHH + 255) / 256, 256>>>(rep, W);

    dim3 g2(16, TT);
    k_main2<<<g2, 256, SMEM_MAIN>>>(E);

    dim3 g3(16, 16);
    k_acc2<<<g3, 256, SMEM_ACC2>>>(out, out_size);
}

// round 13
// speedup vs baseline: 1.9437x; 1.0685x over previous
#include <cuda_runtime.h>
#include <cuda_bf16.h>
#include <math.h>
#include <cstdint>

#define TT  30
#define BBN 2048
#define DD  256
#define DHH 128

typedef unsigned long long u64;
typedef unsigned int       u32;
typedef unsigned short     u16;

#if defined(__CUDA_ARCH_FEAT_SM103_ALL) || defined(__CUDA_ARCH_FEAT_SM100_ALL) || defined(__CUDA_ARCH_FEAT_SM101_ALL)
#define USE_TCGEN05 1
#else
#define USE_TCGEN05 0
#endif

// Fixed softmax shift 64 (proven R7): no overflow, FTZ-dropped terms >=55
// e-folds below any row max, log(0) impossible via clamp.
#define SOFT_SHIFT 64.0f
#define L2E        1.4426950408889634f
#define SHIFT_L2E  (-64.0f * 1.4426950408889634f)

// ---------------------------------------------------------------------------
__device__ float g_lse29[BBN];
__device__ float g_nce[TT * 16];
__device__ u64   g_win[BBN];
__device__ int   g_done = 0;
__device__ u16   g_repB[16 * 32768];       // per 128-col chunk: [hi 16K][lo 16K], swizzled
__device__ u16   g_WB[TT * 2 * 32768];     // per (t,khalf): [hi][lo] W^T tile, swizzled
__device__ u16   g_A29B[16 * 32768];       // per 128-row block: [hi][lo] A29, swizzled

// ---------------------------------------------------------------------------
__device__ __forceinline__ u16 f2bu(float f) {
    __nv_bfloat16 b = __float2bfloat16(f);
    return reinterpret_cast<u16&>(b);
}
__device__ __forceinline__ float b2f(u16 u) {
    __nv_bfloat16 b = reinterpret_cast<__nv_bfloat16&>(u);
    return __bfloat162float(b);
}
__device__ __forceinline__ int swz_idx(int m, int k) {
    int byte = (((m >> 3) + ((k >> 6) << 4)) << 10) + ((m & 7) << 7) + ((k & 63) << 1);
    byte ^= (byte >> 3) & 0x70;
    return byte >> 1;
}
__device__ __forceinline__ float ex2f(float x) {
    float r; asm("ex2.approx.ftz.f32 %0, %1;" : "=f"(r) : "f"(x)); return r;
}
__device__ __forceinline__ uint2 pack_hi4(float a, float b, float c, float d) {
    return make_uint2((u32)f2bu(a) | ((u32)f2bu(b) << 16),
                      (u32)f2bu(c) | ((u32)f2bu(d) << 16));
}
__device__ __forceinline__ uint2 pack_lo4(float a, float b, float c, float d) {
    u16 ha = f2bu(a), hb = f2bu(b), hc = f2bu(c), hd = f2bu(d);
    return make_uint2((u32)f2bu(a - b2f(ha)) | ((u32)f2bu(b - b2f(hb)) << 16),
                      (u32)f2bu(c - b2f(hc)) | ((u32)f2bu(d - b2f(hd)) << 16));
}

// ---------------------------------------------------------------------------
// Pre-kernel, vectorized: each thread converts 4 consecutive k-values and
// writes one uint2 per hi/lo plane (SW128 XOR permutes 16B blocks only, so
// 8B-aligned quads stay contiguous).
// ---------------------------------------------------------------------------
__global__ void k_pre(const float* __restrict__ rep, const float* __restrict__ W) {
    int gid = blockIdx.x * blockDim.x + threadIdx.x;

    if (gid < BBN * DHH / 4) {                 // rep: [c][k], k contiguous
        int c  = gid >> 5;
        int k  = (gid & 31) * 4;
        float4 v = *(const float4*)(rep + c * DHH + k);
        int cb = c >> 7, cl = c & 127;
        u16* base = g_repB + cb * 32768;
        int si = swz_idx(cl, k);
        *(uint2*)(base + si)         = pack_hi4(v.x, v.y, v.z, v.w);
        *(uint2*)(base + 16384 + si) = pack_lo4(v.x, v.y, v.z, v.w);
        if (gid < BBN) g_win[gid] = 0ULL;
    }

    if (gid < TT * DD * DHH / 4) {             // W: [t][d][h]; 4 consecutive d
        int t  = gid >> 13;                    // 8192 items per t
        int r  = gid & 8191;
        int h  = r & 127;
        int d  = (r >> 7) * 4;
        const float* Wp = W + (size_t)t * DD * DHH + (size_t)d * DHH + h;
        float w0 = Wp[0], w1 = Wp[DHH], w2 = Wp[2 * DHH], w3 = Wp[3 * DHH];
        int half = d >> 7, kl = d & 127;
        u16* base = g_WB + t * 65536 + half * 32768;
        int si = swz_idx(h, kl);
        *(uint2*)(base + si)         = pack_hi4(w0, w1, w2, w3);
        *(uint2*)(base + 16384 + si) = pack_lo4(w0, w1, w2, w3);
    }
}

#if USE_TCGEN05
// ===========================================================================
__device__ __forceinline__ u32 elect_one_pred() {
    u32 pred;
    asm volatile("{\n\t.reg .pred p;\n\telect.sync _|p, 0xFFFFFFFF;\n\tselp.b32 %0, 1, 0, p;\n\t}" : "=r"(pred));
    return pred;
}
__device__ __forceinline__ u32 smem_to_u32(const void* p) {
    u32 a;
    asm("{ .reg .u64 t; cvta.to.shared.u64 t, %1; cvt.u32.u64 %0, t; }" : "=r"(a) : "l"(p));
    return a;
}
#define TCGEN05_ALLOC(sa, n) \
    asm volatile("tcgen05.alloc.cta_group::1.sync.aligned.shared::cta.b32 [%0], %1;" :: "r"((u32)(sa)), "r"((u32)(n)) : "memory")
#define TCGEN05_DEALLOC(ta, n) \
    asm volatile("tcgen05.dealloc.cta_group::1.sync.aligned.b32 %0, %1;" :: "r"(ta), "r"((u32)(n)))
#define TCGEN05_RELINQ() \
    asm volatile("tcgen05.relinquish_alloc_permit.cta_group::1.sync.aligned;")
#define TCGEN05_COMMIT(mb) \
    asm volatile("tcgen05.commit.cta_group::1.mbarrier::arrive::one.shared::cluster.b64 [%0];" :: "r"((u32)(mb)) : "memory")
#define TCGEN05_FENCE_BEFORE()  asm volatile("tcgen05.fence::before_thread_sync;" ::: "memory")
#define TCGEN05_FENCE_AFTER()   asm volatile("tcgen05.fence::after_thread_sync;" ::: "memory")
#define TCGEN05_WAIT_LD()       asm volatile("tcgen05.wait::ld.sync.aligned;" ::: "memory")
#define FENCE_PROXY()           asm volatile("fence.proxy.async.shared::cta;" ::: "memory")
#define MBARRIER_INIT(mb, cnt) \
    asm volatile("mbarrier.init.shared.b64 [%0], %1;" :: "r"((u32)(mb)), "r"((u32)(cnt)) : "memory")
#define MBARRIER_INVAL(mb) \
    asm volatile("mbarrier.inval.shared.b64 [%0];" :: "r"((u32)(mb)) : "memory")
#define MBARRIER_EXPECT_TX(mb, bytes) \
    asm volatile("mbarrier.arrive.expect_tx.shared.b64 _, [%0], %1;" :: "r"((u32)(mb)), "r"((u32)(bytes)) : "memory")
#define MBARRIER_WAIT_PARITY(mb, ph) do {                                          \
    u32 _m = (u32)(mb); u32 _p = (u32)(ph); u32 _d;                                \
    asm volatile("{\n\t.reg .pred p;\n\t"                                          \
        "mbarrier.try_wait.parity.acquire.cta.shared::cta.b64 p, [%1], %2;\n\t"    \
        "selp.b32 %0, 1, 0, p;\n\t}" : "=r"(_d) : "r"(_m), "r"(_p) : "memory");    \
    if (!_d) {                                                                     \
        asm volatile("{\n\t.reg .pred P1;\n\t"                                     \
        "WL_%=:\n\t"                                                               \
        "mbarrier.try_wait.parity.acquire.cta.shared::cta.b64 P1, [%0], %1, 0x989680;\n\t" \
        "@P1 bra.uni WD_%=;\n\t"                                                   \
        "bra.uni WL_%=;\n\t"                                                       \
        "WD_%=:\n\t}" :: "r"(_m), "r"(_p) : "memory");                             \
    }                                                                              \
} while (0)

// Plain bulk async copy gmem->smem (pre-swizzled data; no tensor map).
#define BULK_G2S(dst, src, bytes, mb) \
    asm volatile("cp.async.bulk.shared::cta.global.mbarrier::complete_tx::bytes [%0], [%1], %2, [%3];" \
        :: "r"((u32)(dst)), "l"((const void*)(src)), "r"((u32)(bytes)), "r"((u32)(mb)) : "memory")

#define TCGEN05_LD_32X32B_X32(r, ta) \
    asm volatile( \
        "tcgen05.ld.sync.aligned.32x32b.x32.b32 " \
        "{%0, %1, %2, %3, %4, %5, %6, %7, " \
        " %8, %9, %10, %11, %12, %13, %14, %15, " \
        " %16, %17, %18, %19, %20, %21, %22, %23, " \
        " %24, %25, %26, %27, %28, %29, %30, %31}, [%32];" \
        : "=r"((r)[0]),  "=r"((r)[1]),  "=r"((r)[2]),  "=r"((r)[3]), \
          "=r"((r)[4]),  "=r"((r)[5]),  "=r"((r)[6]),  "=r"((r)[7]), \
          "=r"((r)[8]),  "=r"((r)[9]),  "=r"((r)[10]), "=r"((r)[11]), \
          "=r"((r)[12]), "=r"((r)[13]), "=r"((r)[14]), "=r"((r)[15]), \
          "=r"((r)[16]), "=r"((r)[17]), "=r"((r)[18]), "=r"((r)[19]), \
          "=r"((r)[20]), "=r"((r)[21]), "=r"((r)[22]), "=r"((r)[23]), \
          "=r"((r)[24]), "=r"((r)[25]), "=r"((r)[26]), "=r"((r)[27]), \
          "=r"((r)[28]), "=r"((r)[29]), "=r"((r)[30]), "=r"((r)[31]) \
        : "r"(ta))

__device__ __forceinline__ void mma_f16_ss(u32 d, u64 ad, u64 bd, u32 idesc, u32 en) {
    asm volatile(
        "{\n\t.reg .pred p;\n\tsetp.ne.u32 p, %5, 0;\n\t"
        "tcgen05.mma.cta_group::1.kind::f16 [%0], %1, %2, %3, {%4, %4, %4, %4}, p;\n\t}"
        :: "r"(d), "l"(ad), "l"(bd), "r"(idesc), "r"(0u), "r"(en) : "memory");
}

static constexpr u64 DESC_BASE =
    (u64(2) << 61) | (u64(1) << 46) | (u64(64) << 32) | (u64(1) << 16);
#define MK_DESC(a) (DESC_BASE | ((u64)((a) >> 4) & 0x3FFF))
#define IDESC 0x8200490u     // F32 accum, BF16xBF16, M=128, N=128

__device__ __forceinline__ void mma_pass8(u32 d, u64 ad, u64 bd, u32 en0) {
#pragma unroll
    for (int j = 0; j < 8; ++j) {
        u64 off = (u64)((j >> 2) * 1024 + (j & 3) * 2);
        mma_f16_ss(d, ad + off, bd + off, IDESC, j == 0 ? en0 : 1u);
    }
}
#endif  // USE_TCGEN05

// ---------------------------------------------------------------------------
// SMEM map (main kernel)
// ---------------------------------------------------------------------------
#define SM_TMEMPTR 0
#define SM_MG      8         // MMA-done mbar (GEMM1)
#define SM_FS      16        // MMA-done mbar (GEMM2, parity per chunk)
#define SM_WF      24        // W bulk-copy full mbar
#define SM_FB(j)   (32 + 8 * (j))   // B chunk full mbars, j=0..3 (32..56)
#define SM_DIAG    64        // 128 f32
#define SM_MS      576       // 256 f32
#define SM_RED     1600      // 4 f32
#define SM_A       4096      // 32KB: E-hi stage / A-hi
#define SM_B(j)    (36864 + 32768 * (j))    // 4 x 32KB B buffers
#define SMEM_MAIN  167936

#define SA_TMEMPTR 0
#define SA_MB      8
#define SA_LAST    16
#define SA_CP      24
#define SA_LSE     64
#define SA_RH      1024
#define SA_RL      33792
#define SA_AH      66560
#define SA_AL      99328
#define SMEM_ACC2  132096

#if USE_TCGEN05
__device__ __forceinline__ void stage_E(const float* __restrict__ Et, int base_b, int dk,
                                        char* smc, int tid) {
    int row = tid >> 1;
    int cs  = (tid & 1) * 64;
    const float4* src = (const float4*)(Et + (size_t)(base_b + row) * DD + dk + cs);
    u16* hb = (u16*)(smc + SM_A);
#pragma unroll
    for (int q = 0; q < 16; ++q) {
        float4 v = src[q];
        int k = cs + q * 4;
        *(uint2*)(hb + swz_idx(row, k)) = pack_hi4(v.x, v.y, v.z, v.w);
    }
}
#endif

// ---------------------------------------------------------------------------
// Main fused kernel: one CTA per (t, 128-row block). TMA-fed 4-deep B
// pipeline; per-chunk __syncthreads (proven safe ordering from R10).
// ---------------------------------------------------------------------------
__global__ void __launch_bounds__(256, 1)
k_main2(const float* __restrict__ E) {
    extern __shared__ char smc[];
#if USE_TCGEN05
    const u32 sb = smem_to_u32(smc);
    float* sDiag = (float*)(smc + SM_DIAG);
    float* sMS   = (float*)(smc + SM_MS);
    float* sRed  = (float*)(smc + SM_RED);

    const int t      = blockIdx.y;
    const int rb     = blockIdx.x;
    const int base_b = rb * 128;
    const int tid    = threadIdx.x;
    const int wid    = tid >> 5;
    const int lane   = tid & 31;
    const int sub    = wid & 3;
    const int chalf  = wid >> 2;
    const int r_loc  = sub * 32 + lane;

    const float* Et = E + (size_t)t * BBN * DD;

    if (wid == 0) TCGEN05_ALLOC(sb + SM_TMEMPTR, 512);
    if (tid == 0) {
        MBARRIER_INIT(sb + SM_MG, 1);
        MBARRIER_INIT(sb + SM_FS, 1);
        MBARRIER_INIT(sb + SM_WF, 1);
#pragma unroll
        for (int j = 0; j < 4; ++j) MBARRIER_INIT(sb + SM_FB(j), 1);
    }
    __syncthreads();
    u32 tb;
    asm volatile("ld.shared.b32 %0, [%1];" : "=r"(tb) : "r"(sb + SM_TMEMPTR));

    const u64 dA = MK_DESC(sb + SM_A);
    u64 dB[4];
#pragma unroll
    for (int j = 0; j < 4; ++j) dB[j] = MK_DESC(sb + SM_B(j));

    // Kick off W copy (hi0,lo0,hi1,lo1 = 128KB) into B0..B3.
    if (wid == 0 && elect_one_pred()) {
        MBARRIER_EXPECT_TX(sb + SM_WF, 131072);
        BULK_G2S(sb + SM_B(0), g_WB + t * 65536, 131072, sb + SM_WF);
    }

    // ------------- GEMM1 (2-pass): A = Eh·(Wh+Wl), two K-halves -----------
    stage_E(Et, base_b, 0, smc, tid);
    FENCE_PROXY();
    __syncthreads();
    if (wid == 0 && elect_one_pred()) {
        MBARRIER_WAIT_PARITY(sb + SM_WF, 0);
        mma_pass8(tb, dA, dB[0], 0u);
        mma_pass8(tb, dA, dB[1], 1u);
        TCGEN05_COMMIT(sb + SM_MG);
    }
    MBARRIER_WAIT_PARITY(sb + SM_MG, 0);

    stage_E(Et, base_b, 128, smc, tid);
    FENCE_PROXY();
    __syncthreads();
    if (wid == 0 && elect_one_pred()) {
        mma_pass8(tb, dA, dB[2], 1u);
        mma_pass8(tb, dA, dB[3], 1u);
        TCGEN05_COMMIT(sb + SM_MG);
    }
    MBARRIER_WAIT_PARITY(sb + SM_MG, 1);
    TCGEN05_FENCE_AFTER();
    __syncthreads();

    // ------------- A epilogue: TMEM -> A-hi swizzled in SM_A --------------
    {
        u32 a0[32], a1[32];
        TCGEN05_LD_32X32B_X32(a0, tb + chalf * 64);
        TCGEN05_LD_32X32B_X32(a1, tb + chalf * 64 + 32);
        TCGEN05_WAIT_LD();
        u16* hb = (u16*)(smc + SM_A);
#pragma unroll
        for (int q = 0; q < 8; ++q) {
            int k0 = chalf * 64 + q * 4;
            float v0 = __uint_as_float(a0[4 * q]),     v1 = __uint_as_float(a0[4 * q + 1]);
            float v2 = __uint_as_float(a0[4 * q + 2]), v3 = __uint_as_float(a0[4 * q + 3]);
            *(uint2*)(hb + swz_idx(r_loc, k0)) = pack_hi4(v0, v1, v2, v3);
            int k1 = k0 + 32;
            float w0 = __uint_as_float(a1[4 * q]),     w1 = __uint_as_float(a1[4 * q + 1]);
            float w2 = __uint_as_float(a1[4 * q + 2]), w3 = __uint_as_float(a1[4 * q + 3]);
            *(uint2*)(hb + swz_idx(r_loc, k1)) = pack_hi4(w0, w1, w2, w3);
        }
        if (t == TT - 1) {   // hi/lo split for the accuracy pass
            u16* gh = g_A29B + rb * 32768;
            u16* gl = gh + 16384;
#pragma unroll
            for (int j = 0; j < 32; ++j) {
                float v = __uint_as_float(a0[j]);
                int k = chalf * 64 + j;
                u16 hi = f2bu(v);
                gh[swz_idx(r_loc, k)] = hi;
                gl[swz_idx(r_loc, k)] = f2bu(v - b2f(hi));
                float w = __uint_as_float(a1[j]);
                int kk = k + 32;
                u16 hi2 = f2bu(w);
                gh[swz_idx(r_loc, kk)] = hi2;
                gl[swz_idx(r_loc, kk)] = f2bu(w - b2f(hi2));
            }
        }
        TCGEN05_FENCE_BEFORE();
        FENCE_PROXY();
    }
    __syncthreads();

    // ------------- GEMM2: 16 chunks, TMA-fed 4-deep B pipeline ------------
    if (wid == 0 && elect_one_pred()) {
#pragma unroll
        for (int j = 0; j < 4; ++j) {          // prefetch chunks 0..3
            MBARRIER_EXPECT_TX(sb + SM_FB(j), 32768);
            BULK_G2S(sb + SM_B(j), g_repB + j * 32768, 32768, sb + SM_FB(j));
        }
        MBARRIER_WAIT_PARITY(sb + SM_FB(0), 0);
        mma_pass8(tb + 128, dA, dB[0], 0u);    // S(0) -> T ping
        TCGEN05_COMMIT(sb + SM_FS);
    }

    float acc0 = 0.0f, acc1 = 0.0f, acc2 = 0.0f, acc3 = 0.0f;

    for (int i = 0; i < 16; ++i) {
        int p = i & 1;
        MBARRIER_WAIT_PARITY(sb + SM_FS, p);   // MMA(i) done
        TCGEN05_FENCE_AFTER();

        u32 v0[32], v1[32];
        TCGEN05_LD_32X32B_X32(v0, tb + 128 + 128 * p + chalf * 64);
        TCGEN05_LD_32X32B_X32(v1, tb + 128 + 128 * p + chalf * 64 + 32);
        TCGEN05_WAIT_LD();
        TCGEN05_FENCE_BEFORE();
        __syncthreads();                       // all threads drained T(p)

        if (wid == 0 && elect_one_pred()) {
            if (i + 4 <= 15) {                 // MMA(i) done -> B(i&3) free
                MBARRIER_EXPECT_TX(sb + SM_FB(i & 3), 32768);
                BULK_G2S(sb + SM_B(i & 3), g_repB + (i + 4) * 32768, 32768,
                         sb + SM_FB(i & 3));
            }
            if (i < 15) {                      // issue MMA(i+1) -> T(p^1)
                int j = (i + 1) & 3;
                MBARRIER_WAIT_PARITY(sb + SM_FB(j), ((i + 1) >> 2) & 1);
                mma_pass8(tb + 128 + 128 * (p ^ 1), dA, dB[j], 0u);
                TCGEN05_COMMIT(sb + SM_FS);
            }
        }

        if (i == rb) {   // diagonal capture
            int jd = r_loc - chalf * 64;
#pragma unroll
            for (int j = 0; j < 32; ++j) {
                if (j == jd)      sDiag[r_loc] = __uint_as_float(v0[j]);
                if (j + 32 == jd) sDiag[r_loc] = __uint_as_float(v1[j]);
            }
        }

        // sum += exp(s - 64); 4 independent accumulator chains
#pragma unroll
        for (int j = 0; j < 32; j += 4) {
            acc0 += ex2f(fmaf(__uint_as_float(v0[j]),     L2E, SHIFT_L2E));
            acc1 += ex2f(fmaf(__uint_as_float(v0[j + 1]), L2E, SHIFT_L2E));
            acc2 += ex2f(fmaf(__uint_as_float(v0[j + 2]), L2E, SHIFT_L2E));
            acc3 += ex2f(fmaf(__uint_as_float(v0[j + 3]), L2E, SHIFT_L2E));
        }
#pragma unroll
        for (int j = 0; j < 32; j += 4) {
            acc0 += ex2f(fmaf(__uint_as_float(v1[j]),     L2E, SHIFT_L2E));
            acc1 += ex2f(fmaf(__uint_as_float(v1[j + 1]), L2E, SHIFT_L2E));
            acc2 += ex2f(fmaf(__uint_as_float(v1[j + 2]), L2E, SHIFT_L2E));
            acc3 += ex2f(fmaf(__uint_as_float(v1[j + 3]), L2E, SHIFT_L2E));
        }
    }
    __syncthreads();

    sMS[r_loc * 2 + chalf] = (acc0 + acc1) + (acc2 + acc3);
    __syncthreads();

    if (tid < 128) {
        float sum = fmaxf(sMS[tid * 2] + sMS[tid * 2 + 1], 1e-35f);
        float lse = SOFT_SHIFT + __logf(sum);
        if (t == TT - 1) g_lse29[base_b + tid] = lse;
        float part = sDiag[tid] - lse;
#pragma unroll
        for (int o = 1; o < 32; o <<= 1)
            part += __shfl_xor_sync(0xffffffffu, part, o);
        if ((tid & 31) == 0) sRed[tid >> 5] = part;
    }
    __syncthreads();
    if (tid == 0)
        g_nce[t * 16 + rb] = sRed[0] + sRed[1] + sRed[2] + sRed[3];

    if (tid == 0) {
        MBARRIER_INVAL(sb + SM_MG);
        MBARRIER_INVAL(sb + SM_FS);
        MBARRIER_INVAL(sb + SM_WF);
#pragma unroll
        for (int j = 0; j < 4; ++j) MBARRIER_INVAL(sb + SM_FB(j));
    }
    __syncthreads();
    if (wid == 0) {
        TCGEN05_RELINQ();
        TCGEN05_DEALLOC(tb, 512);
    }
#endif
}

// ---------------------------------------------------------------------------
// Accuracy pass (t=29) on tensor cores (TMA-fed) + fused finalize
// ---------------------------------------------------------------------------
__global__ void __launch_bounds__(256, 1)
k_acc2(float* __restrict__ out, int out_size) {
    extern __shared__ char smc[];
#if USE_TCGEN05
    const u32 sb = smem_to_u32(smc);
    float* sLse = (float*)(smc + SA_LSE);
    int*   sLast = (int*)(smc + SA_LAST);

    const int cb  = blockIdx.x;
    const int bb  = blockIdx.y;
    const int tid = threadIdx.x;
    const int wid = tid >> 5;
    const int lane = tid & 31;
    const int sub = wid & 3;
    const int chalf = wid >> 2;
    const int r_loc = sub * 32 + lane;

    if (wid == 0) TCGEN05_ALLOC(sb + SA_TMEMPTR, 128);
    if (tid == 0) {
        MBARRIER_INIT(sb + SA_MB, 1);
        MBARRIER_INIT(sb + SA_CP, 1);
    }
    __syncthreads();
    u32 tb;
    asm volatile("ld.shared.b32 %0, [%1];" : "=r"(tb) : "r"(sb + SA_TMEMPTR));

    if (wid == 0 && elect_one_pred()) {
        MBARRIER_EXPECT_TX(sb + SA_CP, 131072);
        BULK_G2S(sb + SA_RH, g_repB + cb * 32768, 65536, sb + SA_CP);   // hi+lo
        BULK_G2S(sb + SA_AH, g_A29B + bb * 32768, 65536, sb + SA_CP);   // hi+lo
    }
    if (tid < 128) sLse[tid] = g_lse29[bb * 128 + tid];
    __syncthreads();

    if (wid == 0 && elect_one_pred()) {
        MBARRIER_WAIT_PARITY(sb + SA_CP, 0);
        u64 dRH = MK_DESC(sb + SA_RH), dRL = MK_DESC(sb + SA_RL);
        u64 dAH = MK_DESC(sb + SA_AH), dAL = MK_DESC(sb + SA_AL);
        mma_pass8(tb, dRH, dAH, 0u);
        mma_pass8(tb, dRH, dAL, 1u);
        mma_pass8(tb, dRL, dAH, 1u);
        TCGEN05_COMMIT(sb + SA_MB);
    }
    MBARRIER_WAIT_PARITY(sb + SA_MB, 0);
    TCGEN05_FENCE_AFTER();

    u32 v0[32], v1[32];
    TCGEN05_LD_32X32B_X32(v0, tb + chalf * 64);
    TCGEN05_LD_32X32B_X32(v1, tb + chalf * 64 + 32);
    TCGEN05_WAIT_LD();

    int c = cb * 128 + r_loc;
    u64 best = 0ULL;
#pragma unroll
    for (int j = 0; j < 32; ++j) {
        float v = __uint_as_float(v0[j]) - sLse[chalf * 64 + j];
        u32 u = __float_as_uint(v);
        u = (u & 0x80000000u) ? ~u : (u | 0x80000000u);
        u64 key = ((u64)u << 32) | (u32)(bb * 128 + chalf * 64 + j);
        if (key > best) best = key;
    }
#pragma unroll
    for (int j = 0; j < 32; ++j) {
        float v = __uint_as_float(v1[j]) - sLse[chalf * 64 + 32 + j];
        u32 u = __float_as_uint(v);
        u = (u & 0x80000000u) ? ~u : (u | 0x80000000u);
        u64 key = ((u64)u << 32) | (u32)(bb * 128 + chalf * 64 + 32 + j);
        if (key > best) best = key;
    }
    atomicMax(&g_win[c], best);

    TCGEN05_FENCE_BEFORE();
    __syncthreads();
    if (tid == 0) {
        MBARRIER_INVAL(sb + SA_MB);
        MBARRIER_INVAL(sb + SA_CP);
    }
    __syncthreads();
    if (wid == 0) {
        TCGEN05_RELINQ();
        TCGEN05_DEALLOC(tb, 128);
    }

    __threadfence();
    if (tid == 0) {
        int done = atomicAdd(&g_done, 1);
        *sLast = (done == gridDim.x * gridDim.y - 1);
    }
    __syncthreads();
    if (*sLast) {
        __shared__ double rd[256];
        __shared__ int    ri[256];
        int cnt = 0;
        for (int cc = tid; cc < BBN; cc += 256)
            cnt += ((u32)(g_win[cc] & 0xffffffffULL) == (u32)cc);
        double sum = 0.0;
        for (int i = tid; i < TT * 16; i += 256) sum += (double)g_nce[i];
        rd[tid] = sum; ri[tid] = cnt;
        __syncthreads();
        for (int st = 128; st > 0; st >>= 1) {
            if (tid < st) { rd[tid] += rd[tid + st]; ri[tid] += ri[tid + st]; }
            __syncthreads();
        }
        if (tid == 0) {
            out[0] = (float)ri[0] / (float)BBN;
            out[1] = (float)(rd[0] / (-(double)(BBN * TT)));
            out[2] = (float)BBN;
            out[3] = (float)(BBN * TT);
            for (int i = 4; i < out_size; ++i) out[i] = 0.0f;
            g_done = 0;
        }
    }
#endif
}

// ---------------------------------------------------------------------------
extern "C" void kernel_launch(void* const* d_in, const int* in_sizes, int n_in,
                              void* d_out, int out_size) {
    const float* E   = (const float*)d_in[0];
    const float* rep = (const float*)d_in[1];
    const float* W   = (const float*)d_in[2];
    // d_in[3] = Wk_b: row-constant shift, cancels in both softmaxes
    float* out = (float*)d_out;

    cudaFuncSetAttribute(k_main2, cudaFuncAttributeMaxDynamicSharedMemorySize, SMEM_MAIN);
    cudaFuncSetAttribute(k_acc2,  cudaFuncAttributeMaxDynamicSharedMemorySize, SMEM_ACC2);

    k_pre<<<(TT * DD * DHH / 4 + 255) / 256, 256>>>(rep, W);

    dim3 g2(16, TT);
    k_main2<<<g2, 256, SMEM_MAIN>>>(E);

    dim3 g3(16, 16);
    k_acc2<<<g3, 256, SMEM_ACC2>>>(out, out_size);
}